// round 14
// baseline (speedup 1.0000x reference)
#include <cuda_runtime.h>
#include <cuda_bf16.h>
#include <cstdint>

#define THREADS 128
#define NWARP 4
#define NCOEF 1001
#define NSM 148
#define BLOCKS_PER_SM 6
#define GRID (NSM * BLOCKS_PER_SM)

__device__ __forceinline__ uint32_t cvta_s(const void* p) {
    return (uint32_t)__cvta_generic_to_shared(p);
}
__device__ __forceinline__ void ldm_x2(uint32_t& r0, uint32_t& r1, uint32_t addr) {
    asm volatile("ldmatrix.sync.aligned.m8n8.x2.shared.b16 {%0,%1}, [%2];"
                 : "=r"(r0), "=r"(r1) : "r"(addr));
}
__device__ __forceinline__ void mma(float* d, uint32_t a0, uint32_t a1,
                                    uint32_t a2, uint32_t a3,
                                    uint32_t b0, uint32_t b1) {
    asm volatile("mma.sync.aligned.m16n8k16.row.col.f32.bf16.bf16.f32 "
                 "{%0,%1,%2,%3}, {%4,%5,%6,%7}, {%8,%9}, {%0,%1,%2,%3};"
                 : "+f"(d[0]), "+f"(d[1]), "+f"(d[2]), "+f"(d[3])
                 : "r"(a0), "r"(a1), "r"(a2), "r"(a3), "r"(b0), "r"(b1));
}
__device__ __forceinline__ void mma_z(float* d, uint32_t a0, uint32_t a1,
                                      uint32_t a2, uint32_t a3,
                                      uint32_t b0, uint32_t b1) {
    asm volatile("mma.sync.aligned.m16n8k16.row.col.f32.bf16.bf16.f32 "
                 "{%0,%1,%2,%3}, {%4,%5,%6,%7}, {%8,%9}, {%10,%10,%10,%10};"
                 : "=f"(d[0]), "=f"(d[1]), "=f"(d[2]), "=f"(d[3])
                 : "r"(a0), "r"(a1), "r"(a2), "r"(a3), "r"(b0), "r"(b1),
                   "f"(0.0f));
}

// Packed bf16x2 A-fragment pairs at exponents (2cL+off, 2cL+1+off),
// off = 0,8,16,24; hi part + lo residual. cvt low half = even exponent.
__device__ __forceinline__ void frag_powers(float xe, int cL,
                                            uint32_t hi[4], uint32_t lo[4]) {
    float x2 = xe * xe, x4 = x2 * x2, x8 = x4 * x4;
    float x16 = x8 * x8, x24 = x16 * x8;
    float b = (cL == 0) ? 1.0f : (cL == 1) ? x2 : (cL == 2) ? x4 : x4 * x2;
    float p0 = b, p1 = b * xe;
    float ev[4] = {p0, p0 * x8, p0 * x16, p0 * x24};
    float od[4] = {p1, p1 * x8, p1 * x16, p1 * x24};
    #pragma unroll
    for (int j = 0; j < 4; j++) {
        __nv_bfloat162 h2 = __floats2bfloat162_rn(ev[j], od[j]);
        uint32_t hb = *reinterpret_cast<uint32_t*>(&h2);
        float f0 = __uint_as_float(hb << 16);
        float f1 = __uint_as_float(hb & 0xFFFF0000u);
        __nv_bfloat162 l2 = __floats2bfloat162_rn(ev[j] - f0, od[j] - f1);
        hi[j] = hb;
        lo[j] = *reinterpret_cast<uint32_t*>(&l2);
    }
}

__device__ __forceinline__ float horner8(float4 a, float4 b, float q) {
    float h = b.w;
    h = fmaf(h, q, b.z); h = fmaf(h, q, b.y); h = fmaf(h, q, b.x);
    h = fmaf(h, q, a.w); h = fmaf(h, q, a.z); h = fmaf(h, q, a.y);
    return fmaf(h, q, a.x);
}

__global__ __launch_bounds__(THREADS, BLOCKS_PER_SM)
void poly_tc_kernel(const float* __restrict__ xg,
                    const float* __restrict__ wg,
                    float* __restrict__ out,
                    int ntiles) {
    __shared__ __align__(128) unsigned char smW[32 * 128];
    __shared__ __align__(128) unsigned char smS[NWARP][32 * 128];

    const int tid  = threadIdx.x;
    const int wid  = tid >> 5;
    const int lane = tid & 31;
    const int g    = lane >> 2;
    const int cL   = lane & 3;

    // ---- once-per-block prologue: W_hi/W_lo tiles + persistent B frags ----
    for (int i = tid; i < 1024; i += THREADS) {
        float v = (i < NCOEF) ? wg[i] : 0.0f;
        __nv_bfloat16 hb = __float2bfloat16_rn(v);
        __nv_bfloat16 lb = __float2bfloat16_rn(v - __bfloat162float(hb));
        int n = i >> 5, k = i & 31;
        int ch = k >> 3, byo = (k & 7) * 2;
        *(__nv_bfloat16*)(smW + n * 128 + ((ch ^ (n & 7)) & 7) * 16 + byo) = hb;
        *(__nv_bfloat16*)(smW + n * 128 + (((ch + 4) ^ (n & 7)) & 7) * 16 + byo) = lb;
    }
    __syncthreads();

    uint32_t bf[2][4][2][2];   // [part][t][h][2]
    {
        const uint32_t wbase = cvta_s(smW);
        const int lr = lane & 15;
        #pragma unroll
        for (int part = 0; part < 2; part++)
            #pragma unroll
            for (int t = 0; t < 4; t++)
                #pragma unroll
                for (int h = 0; h < 2; h++) {
                    int row = 8 * t + (lr & 7);
                    int ch  = part * 4 + 2 * h + (lr >> 3);
                    uint32_t addr = wbase + row * 128 + ((ch ^ (row & 7)) & 7) * 16;
                    ldm_x2(bf[part][t][h][0], bf[part][t][h][1], addr);
                }
    }

    const uint32_t sbase = cvta_s(smS[wid]);
    const int warp_gid = blockIdx.x * NWARP + wid;
    const int stride   = gridDim.x * NWARP;

    // Prefetched state: own x + the 4 row-x values this thread's fragments
    // need (L1-hit broadcast loads; replaces SHFLs on the critical path).
    float x_cur = 0.0f, xe_cur[4] = {0, 0, 0, 0};
    if (warp_gid < ntiles) {
        const float* p = xg + warp_gid * 32;
        x_cur = p[lane];
        xe_cur[0] = p[g];      xe_cur[1] = p[g + 8];
        xe_cur[2] = p[g + 16]; xe_cur[3] = p[g + 24];
    }

    #pragma unroll 1
    for (int tile = warp_gid; tile < ntiles; tile += stride) {
        const int nt = tile + stride;
        float x_nxt = 0.0f, xe_nxt[4] = {0, 0, 0, 0};
        if (nt < ntiles) {
            const float* p = xg + nt * 32;
            x_nxt = p[lane];
            xe_nxt[0] = p[g];      xe_nxt[1] = p[g + 8];
            xe_nxt[2] = p[g + 16]; xe_nxt[3] = p[g + 24];
        }

        const float xt = x_cur;
        float t2 = xt * xt, t4 = t2 * t2, t8 = t4 * t4, t16 = t8 * t8;
        const float q = t16 * t16;   // x^32, own element

        __syncwarp();   // prior tile's S readback done before overwrite

        #pragma unroll
        for (int m = 0; m < 2; m++) {
            uint32_t h0[4], l0[4], h1[4], l1[4];
            frag_powers(xe_cur[2 * m], cL, h0, l0);       // row 16m+g
            frag_powers(xe_cur[2 * m + 1], cL, h1, l1);   // row 16m+g+8

            #pragma unroll
            for (int t = 0; t < 4; t++) {
                // two 3-deep chains instead of one 6-deep chain
                float Dh[4], Dl[4];
                mma_z(Dh, h0[0], h1[0], h0[1], h1[1], bf[0][t][0][0], bf[0][t][0][1]);
                mma  (Dh, h0[2], h1[2], h0[3], h1[3], bf[0][t][1][0], bf[0][t][1][1]);
                mma  (Dh, l0[0], l1[0], l0[1], l1[1], bf[0][t][0][0], bf[0][t][0][1]);
                mma_z(Dl, l0[2], l1[2], l0[3], l1[3], bf[0][t][1][0], bf[0][t][1][1]);
                mma  (Dl, h0[0], h1[0], h0[1], h1[1], bf[1][t][0][0], bf[1][t][0][1]);
                mma  (Dl, h0[2], h1[2], h0[3], h1[3], bf[1][t][1][0], bf[1][t][1][1]);

                int ch  = 2 * t + (cL >> 1);
                int sub = 8 * (cL & 1);
                int r0  = 16 * m + g;
                int r1  = r0 + 8;
                uint32_t a0 = sbase + r0 * 128 + ((ch ^ (r0 & 7)) & 7) * 16 + sub;
                uint32_t a1 = sbase + r1 * 128 + ((ch ^ (r1 & 7)) & 7) * 16 + sub;
                asm volatile("st.shared.v2.b32 [%0], {%1,%2};"
                             :: "r"(a0), "f"(Dh[0] + Dl[0]), "f"(Dh[1] + Dl[1]));
                asm volatile("st.shared.v2.b32 [%0], {%1,%2};"
                             :: "r"(a1), "f"(Dh[2] + Dl[2]), "f"(Dh[3] + Dl[3]));
            }
        }
        __syncwarp();   // S complete before readback

        // Epilogue in two halves (16-reg burst each). s[ch] = S[4ch..4ch+3].
        float q2 = q * q, q4 = q2 * q2, q8 = q4 * q4;
        float C0, C1, C2, C3;
        {
            float4 s0, s1, s2, s3;
            #pragma unroll
            for (int ch = 0; ch < 4; ch++) {
                uint32_t addr = sbase + lane * 128 + ((ch ^ (lane & 7)) & 7) * 16;
                float4* d = (ch == 0) ? &s0 : (ch == 1) ? &s1 : (ch == 2) ? &s2 : &s3;
                asm volatile("ld.shared.v4.f32 {%0,%1,%2,%3}, [%4];"
                             : "=f"(d->x), "=f"(d->y), "=f"(d->z), "=f"(d->w)
                             : "r"(addr));
            }
            C0 = horner8(s0, s1, q);
            C1 = horner8(s2, s3, q);
        }
        {
            float4 s4, s5, s6, s7;
            #pragma unroll
            for (int ch = 4; ch < 8; ch++) {
                uint32_t addr = sbase + lane * 128 + ((ch ^ (lane & 7)) & 7) * 16;
                float4* d = (ch == 4) ? &s4 : (ch == 5) ? &s5 : (ch == 6) ? &s6 : &s7;
                asm volatile("ld.shared.v4.f32 {%0,%1,%2,%3}, [%4];"
                             : "=f"(d->x), "=f"(d->y), "=f"(d->z), "=f"(d->w)
                             : "r"(addr));
            }
            C2 = horner8(s4, s5, q);
            C3 = horner8(s6, s7, q);
        }
        float y = fmaf(fmaf(fmaf(C3, q8, C2), q8, C1), q8, C0);
        out[tile * 32 + lane] = y;

        x_cur = x_nxt;
        xe_cur[0] = xe_nxt[0]; xe_cur[1] = xe_nxt[1];
        xe_cur[2] = xe_nxt[2]; xe_cur[3] = xe_nxt[3];
    }
}

extern "C" void kernel_launch(void* const* d_in, const int* in_sizes, int n_in,
                              void* d_out, int out_size) {
    const float* x = (const float*)d_in[0];   // (512, 1024) fp32
    const float* w = (const float*)d_in[1];   // (1001,) fp32
    float* out = (float*)d_out;

    const int ntiles = out_size / 32;          // 16384 warp-tiles
    poly_tc_kernel<<<GRID, THREADS>>>(x, w, out, ntiles);
}

// round 16
// speedup vs baseline: 1.0341x; 1.0341x over previous
#include <cuda_runtime.h>
#include <cuda_bf16.h>
#include <cstdint>

#define THREADS 128
#define NWARP 4
#define NCOEF 1001
#define NSM 148
#define BLOCKS_PER_SM 6
#define GRID (NSM * BLOCKS_PER_SM)

// S scratch: 32 rows x 144B (stride 144 = +4 banks/row, conflict-free, no XOR)
#define SROW 144
#define S_WARP_BYTES (32 * SROW)

__device__ __forceinline__ uint32_t cvta_s(const void* p) {
    return (uint32_t)__cvta_generic_to_shared(p);
}
__device__ __forceinline__ void ldm_x2(uint32_t& r0, uint32_t& r1, uint32_t addr) {
    asm volatile("ldmatrix.sync.aligned.m8n8.x2.shared.b16 {%0,%1}, [%2];"
                 : "=r"(r0), "=r"(r1) : "r"(addr));
}
__device__ __forceinline__ void mma(float* d, uint32_t a0, uint32_t a1,
                                    uint32_t a2, uint32_t a3,
                                    uint32_t b0, uint32_t b1) {
    asm volatile("mma.sync.aligned.m16n8k16.row.col.f32.bf16.bf16.f32 "
                 "{%0,%1,%2,%3}, {%4,%5,%6,%7}, {%8,%9}, {%0,%1,%2,%3};"
                 : "+f"(d[0]), "+f"(d[1]), "+f"(d[2]), "+f"(d[3])
                 : "r"(a0), "r"(a1), "r"(a2), "r"(a3), "r"(b0), "r"(b1));
}
__device__ __forceinline__ void mma_z(float* d, uint32_t a0, uint32_t a1,
                                      uint32_t a2, uint32_t a3,
                                      uint32_t b0, uint32_t b1) {
    asm volatile("mma.sync.aligned.m16n8k16.row.col.f32.bf16.bf16.f32 "
                 "{%0,%1,%2,%3}, {%4,%5,%6,%7}, {%8,%9}, {%10,%10,%10,%10};"
                 : "=f"(d[0]), "=f"(d[1]), "=f"(d[2]), "=f"(d[3])
                 : "r"(a0), "r"(a1), "r"(a2), "r"(a3), "r"(b0), "r"(b1),
                   "f"(0.0f));
}
#define STS64_I(base, imm, v0, v1) \
    asm volatile("st.shared.v2.b32 [%0+%3], {%1,%2};" \
                 :: "r"(base), "f"(v0), "f"(v1), "n"(imm))
#define LDS128_I(dst, base, imm) \
    asm volatile("ld.shared.v4.f32 {%0,%1,%2,%3}, [%4+%5];" \
                 : "=f"((dst).x), "=f"((dst).y), "=f"((dst).z), "=f"((dst).w) \
                 : "r"(base), "n"(imm))

// Packed bf16x2 A-fragment pairs at exponents (2cL+off, 2cL+1+off),
// off = 0,8,16,24; hi part + lo residual. cvt low half = even exponent.
__device__ __forceinline__ void frag_powers(float xe, int cL,
                                            uint32_t hi[4], uint32_t lo[4]) {
    float x2 = xe * xe, x4 = x2 * x2, x8 = x4 * x4;
    float x16 = x8 * x8, x24 = x16 * x8;
    float b = (cL == 0) ? 1.0f : (cL == 1) ? x2 : (cL == 2) ? x4 : x4 * x2;
    float p0 = b, p1 = b * xe;
    float ev[4] = {p0, p0 * x8, p0 * x16, p0 * x24};
    float od[4] = {p1, p1 * x8, p1 * x16, p1 * x24};
    #pragma unroll
    for (int j = 0; j < 4; j++) {
        __nv_bfloat162 h2 = __floats2bfloat162_rn(ev[j], od[j]);
        uint32_t hb = *reinterpret_cast<uint32_t*>(&h2);
        float f0 = __uint_as_float(hb << 16);
        float f1 = __uint_as_float(hb & 0xFFFF0000u);
        __nv_bfloat162 l2 = __floats2bfloat162_rn(ev[j] - f0, od[j] - f1);
        hi[j] = hb;
        lo[j] = *reinterpret_cast<uint32_t*>(&l2);
    }
}

__device__ __forceinline__ float horner8(float4 a, float4 b, float q) {
    float h = b.w;
    h = fmaf(h, q, b.z); h = fmaf(h, q, b.y); h = fmaf(h, q, b.x);
    h = fmaf(h, q, a.w); h = fmaf(h, q, a.z); h = fmaf(h, q, a.y);
    return fmaf(h, q, a.x);
}

// One (m, t) unit: 6 accumulating MMAs + 2 immediate-offset STS.64.
// MLIT/TLIT are literal ints so the "n" operands are constant expressions.
#define MMA_T(MLIT, TLIT)                                                        \
    {                                                                            \
        float D[4];                                                              \
        mma_z(D, h0[0], h1[0], h0[1], h1[1], bf[0][TLIT][0][0], bf[0][TLIT][0][1]); \
        mma  (D, h0[2], h1[2], h0[3], h1[3], bf[0][TLIT][1][0], bf[0][TLIT][1][1]); \
        mma  (D, l0[0], l1[0], l0[1], l1[1], bf[0][TLIT][0][0], bf[0][TLIT][0][1]); \
        mma  (D, l0[2], l1[2], l0[3], l1[3], bf[0][TLIT][1][0], bf[0][TLIT][1][1]); \
        mma  (D, h0[0], h1[0], h0[1], h1[1], bf[1][TLIT][0][0], bf[1][TLIT][0][1]); \
        mma  (D, h0[2], h1[2], h0[3], h1[3], bf[1][TLIT][1][0], bf[1][TLIT][1][1]); \
        STS64_I(sb0, (MLIT) * 16 * SROW + (TLIT) * 16, D[0], D[1]);              \
        STS64_I(sb0, (MLIT) * 16 * SROW + 8 * SROW + (TLIT) * 16, D[2], D[3]);   \
    }

#define MMA_M(MLIT)                                                              \
    {                                                                            \
        uint32_t h0[4], l0[4], h1[4], l1[4];                                     \
        frag_powers(xe_cur[2 * (MLIT)], cL, h0, l0);     /* row 16m+g   */       \
        frag_powers(xe_cur[2 * (MLIT) + 1], cL, h1, l1); /* row 16m+g+8 */       \
        MMA_T(MLIT, 0) MMA_T(MLIT, 1) MMA_T(MLIT, 2) MMA_T(MLIT, 3)              \
    }

__global__ __launch_bounds__(THREADS, BLOCKS_PER_SM)
void poly_tc_kernel(const float* __restrict__ xg,
                    const float* __restrict__ wg,
                    float* __restrict__ out,
                    int ntiles) {
    __shared__ __align__(128) unsigned char smW[32 * 128];
    __shared__ __align__(128) unsigned char smS[NWARP][S_WARP_BYTES];

    const int tid  = threadIdx.x;
    const int wid  = tid >> 5;
    const int lane = tid & 31;
    const int g    = lane >> 2;
    const int cL   = lane & 3;

    // ---- once-per-block prologue: W tiles (swizzled) + B fragments ----
    for (int i = tid; i < 1024; i += THREADS) {
        float v = (i < NCOEF) ? wg[i] : 0.0f;
        __nv_bfloat16 hb = __float2bfloat16_rn(v);
        __nv_bfloat16 lb = __float2bfloat16_rn(v - __bfloat162float(hb));
        int n = i >> 5, k = i & 31;
        int ch = k >> 3, byo = (k & 7) * 2;
        *(__nv_bfloat16*)(smW + n * 128 + ((ch ^ (n & 7)) & 7) * 16 + byo) = hb;
        *(__nv_bfloat16*)(smW + n * 128 + (((ch + 4) ^ (n & 7)) & 7) * 16 + byo) = lb;
    }
    __syncthreads();

    uint32_t bf[2][4][2][2];   // [part][t][h][2]
    {
        const uint32_t wbase = cvta_s(smW);
        const int lr = lane & 15;
        #pragma unroll
        for (int part = 0; part < 2; part++)
            #pragma unroll
            for (int t = 0; t < 4; t++)
                #pragma unroll
                for (int h = 0; h < 2; h++) {
                    int row = 8 * t + (lr & 7);
                    int ch  = part * 4 + 2 * h + (lr >> 3);
                    uint32_t addr = wbase + row * 128 + ((ch ^ (row & 7)) & 7) * 16;
                    ldm_x2(bf[part][t][h][0], bf[part][t][h][1], addr);
                }
    }

    // All-immediate S addressing: two loop-invariant base registers.
    // store base: row g, chunk c' = 4u + t at byte 144*row + 64u + 16t + 8e
    const uint32_t sbase = cvta_s(smS[wid]);
    const uint32_t sb0 = sbase + (uint32_t)(g * SROW + 64 * (cL >> 1) + 8 * (cL & 1));
    const uint32_t rb  = sbase + (uint32_t)(lane * SROW);

    const int warp_gid = blockIdx.x * NWARP + wid;
    const int stride   = gridDim.x * NWARP;

    float x_cur = 0.0f, xe_cur[4] = {0, 0, 0, 0};
    if (warp_gid < ntiles) {
        const float* p = xg + warp_gid * 32;
        x_cur = p[lane];
        xe_cur[0] = p[g];      xe_cur[1] = p[g + 8];
        xe_cur[2] = p[g + 16]; xe_cur[3] = p[g + 24];
    }

    #pragma unroll 1
    for (int tile = warp_gid; tile < ntiles; tile += stride) {
        const int nt = tile + stride;
        float x_nxt = 0.0f, xe_nxt[4] = {0, 0, 0, 0};
        if (nt < ntiles) {
            const float* p = xg + nt * 32;
            x_nxt = p[lane];
            xe_nxt[0] = p[g];      xe_nxt[1] = p[g + 8];
            xe_nxt[2] = p[g + 16]; xe_nxt[3] = p[g + 24];
        }

        const float xt = x_cur;
        float t2 = xt * xt, t4 = t2 * t2, t8 = t4 * t4, t16 = t8 * t8;
        const float q = t16 * t16;   // x^32, own element

        __syncwarp();   // prior tile's S readback done before overwrite

        MMA_M(0)
        MMA_M(1)

        __syncwarp();   // S complete before readback

        // Epilogue: j-chunk ch lives at physical c' = 4*(ch&1) + (ch>>1)
        float4 s0, s1, s2, s3, s4, s5, s6, s7;
        LDS128_I(s0, rb, 0);    // ch0 -> c'0
        LDS128_I(s1, rb, 64);   // ch1 -> c'4
        LDS128_I(s2, rb, 16);   // ch2 -> c'1
        LDS128_I(s3, rb, 80);   // ch3 -> c'5
        LDS128_I(s4, rb, 32);   // ch4 -> c'2
        LDS128_I(s5, rb, 96);   // ch5 -> c'6
        LDS128_I(s6, rb, 48);   // ch6 -> c'3
        LDS128_I(s7, rb, 112);  // ch7 -> c'7
        float q2 = q * q, q4 = q2 * q2, q8 = q4 * q4;
        float C0 = horner8(s0, s1, q);
        float C1 = horner8(s2, s3, q);
        float C2 = horner8(s4, s5, q);
        float C3 = horner8(s6, s7, q);
        float y = fmaf(fmaf(fmaf(C3, q8, C2), q8, C1), q8, C0);
        out[tile * 32 + lane] = y;

        x_cur = x_nxt;
        xe_cur[0] = xe_nxt[0]; xe_cur[1] = xe_nxt[1];
        xe_cur[2] = xe_nxt[2]; xe_cur[3] = xe_nxt[3];
    }
}

extern "C" void kernel_launch(void* const* d_in, const int* in_sizes, int n_in,
                              void* d_out, int out_size) {
    const float* x = (const float*)d_in[0];   // (512, 1024) fp32
    const float* w = (const float*)d_in[1];   // (1001,) fp32
    float* out = (float*)d_out;

    const int ntiles = out_size / 32;          // 16384 warp-tiles
    poly_tc_kernel<<<GRID, THREADS>>>(x, w, out, ntiles);
}

// round 17
// speedup vs baseline: 1.0466x; 1.0121x over previous
#include <cuda_runtime.h>
#include <cuda_bf16.h>
#include <cstdint>

#define THREADS 128
#define NWARP 4
#define NCOEF 1001
#define NSM 148
#define GRID (NSM * 5)

// S scratch: 32 rows x 144B (stride 144 = +4 banks/row, conflict-free, no XOR)
#define SROW 144
#define S_WARP_BYTES (32 * SROW)

__device__ __forceinline__ uint32_t cvta_s(const void* p) {
    return (uint32_t)__cvta_generic_to_shared(p);
}
__device__ __forceinline__ void ldm_x2(uint32_t& r0, uint32_t& r1, uint32_t addr) {
    asm volatile("ldmatrix.sync.aligned.m8n8.x2.shared.b16 {%0,%1}, [%2];"
                 : "=r"(r0), "=r"(r1) : "r"(addr));
}
__device__ __forceinline__ void mma(float* d, uint32_t a0, uint32_t a1,
                                    uint32_t a2, uint32_t a3,
                                    uint32_t b0, uint32_t b1) {
    asm volatile("mma.sync.aligned.m16n8k16.row.col.f32.bf16.bf16.f32 "
                 "{%0,%1,%2,%3}, {%4,%5,%6,%7}, {%8,%9}, {%0,%1,%2,%3};"
                 : "+f"(d[0]), "+f"(d[1]), "+f"(d[2]), "+f"(d[3])
                 : "r"(a0), "r"(a1), "r"(a2), "r"(a3), "r"(b0), "r"(b1));
}
__device__ __forceinline__ void mma_z(float* d, uint32_t a0, uint32_t a1,
                                      uint32_t a2, uint32_t a3,
                                      uint32_t b0, uint32_t b1) {
    asm volatile("mma.sync.aligned.m16n8k16.row.col.f32.bf16.bf16.f32 "
                 "{%0,%1,%2,%3}, {%4,%5,%6,%7}, {%8,%9}, {%10,%10,%10,%10};"
                 : "=f"(d[0]), "=f"(d[1]), "=f"(d[2]), "=f"(d[3])
                 : "r"(a0), "r"(a1), "r"(a2), "r"(a3), "r"(b0), "r"(b1),
                   "f"(0.0f));
}
#define STS64_I(base, imm, v0, v1) \
    asm volatile("st.shared.v2.b32 [%0+%3], {%1,%2};" \
                 :: "r"(base), "f"(v0), "f"(v1), "n"(imm))
#define LDS128_I(dst, base, imm) \
    asm volatile("ld.shared.v4.f32 {%0,%1,%2,%3}, [%4+%5];" \
                 : "=f"((dst).x), "=f"((dst).y), "=f"((dst).z), "=f"((dst).w) \
                 : "r"(base), "n"(imm))

// Packed bf16x2 A-fragment pairs at exponents (2cL+off, 2cL+1+off),
// off = 0,8,16,24; hi part + lo residual. cvt low half = even exponent.
__device__ __forceinline__ void frag_powers(float xe, int cL,
                                            uint32_t hi[4], uint32_t lo[4]) {
    float x2 = xe * xe, x4 = x2 * x2, x8 = x4 * x4;
    float x16 = x8 * x8, x24 = x16 * x8;
    float b = (cL == 0) ? 1.0f : (cL == 1) ? x2 : (cL == 2) ? x4 : x4 * x2;
    float p0 = b, p1 = b * xe;
    float ev[4] = {p0, p0 * x8, p0 * x16, p0 * x24};
    float od[4] = {p1, p1 * x8, p1 * x16, p1 * x24};
    #pragma unroll
    for (int j = 0; j < 4; j++) {
        __nv_bfloat162 h2 = __floats2bfloat162_rn(ev[j], od[j]);
        uint32_t hb = *reinterpret_cast<uint32_t*>(&h2);
        float f0 = __uint_as_float(hb << 16);
        float f1 = __uint_as_float(hb & 0xFFFF0000u);
        __nv_bfloat162 l2 = __floats2bfloat162_rn(ev[j] - f0, od[j] - f1);
        hi[j] = hb;
        lo[j] = *reinterpret_cast<uint32_t*>(&l2);
    }
}

__device__ __forceinline__ float horner8(float4 a, float4 b, float q) {
    float h = b.w;
    h = fmaf(h, q, b.z); h = fmaf(h, q, b.y); h = fmaf(h, q, b.x);
    h = fmaf(h, q, a.w); h = fmaf(h, q, a.z); h = fmaf(h, q, a.y);
    return fmaf(h, q, a.x);
}

// One (m, t) unit: 6 accumulating MMAs + 2 immediate-offset STS.64.
#define MMA_T(SB, MLIT, TLIT)                                                    \
    {                                                                            \
        float D[4];                                                              \
        mma_z(D, h0[0], h1[0], h0[1], h1[1], bf[0][TLIT][0][0], bf[0][TLIT][0][1]); \
        mma  (D, h0[2], h1[2], h0[3], h1[3], bf[0][TLIT][1][0], bf[0][TLIT][1][1]); \
        mma  (D, l0[0], l1[0], l0[1], l1[1], bf[0][TLIT][0][0], bf[0][TLIT][0][1]); \
        mma  (D, l0[2], l1[2], l0[3], l1[3], bf[0][TLIT][1][0], bf[0][TLIT][1][1]); \
        mma  (D, h0[0], h1[0], h0[1], h1[1], bf[1][TLIT][0][0], bf[1][TLIT][0][1]); \
        mma  (D, h0[2], h1[2], h0[3], h1[3], bf[1][TLIT][1][0], bf[1][TLIT][1][1]); \
        STS64_I(SB, (MLIT) * 16 * SROW + (TLIT) * 16, D[0], D[1]);               \
        STS64_I(SB, (MLIT) * 16 * SROW + 8 * SROW + (TLIT) * 16, D[2], D[3]);    \
    }

#define MMA_M(SB, XE, MLIT)                                                      \
    {                                                                            \
        uint32_t h0[4], l0[4], h1[4], l1[4];                                     \
        frag_powers((XE)[2 * (MLIT)], cL, h0, l0);     /* row 16m+g   */         \
        frag_powers((XE)[2 * (MLIT) + 1], cL, h1, l1); /* row 16m+g+8 */         \
        MMA_T(SB, MLIT, 0) MMA_T(SB, MLIT, 1) MMA_T(SB, MLIT, 2) MMA_T(SB, MLIT, 3) \
    }

// Epilogue: j-chunk ch lives at physical c' = 4*(ch&1) + (ch>>1)
__device__ __forceinline__ float epilogue(uint32_t rb, float q) {
    float4 s0, s1, s2, s3, s4, s5, s6, s7;
    LDS128_I(s0, rb, 0);    // ch0 -> c'0
    LDS128_I(s1, rb, 64);   // ch1 -> c'4
    LDS128_I(s2, rb, 16);   // ch2 -> c'1
    LDS128_I(s3, rb, 80);   // ch3 -> c'5
    LDS128_I(s4, rb, 32);   // ch4 -> c'2
    LDS128_I(s5, rb, 96);   // ch5 -> c'6
    LDS128_I(s6, rb, 48);   // ch6 -> c'3
    LDS128_I(s7, rb, 112);  // ch7 -> c'7
    float q2 = q * q, q4 = q2 * q2, q8 = q4 * q4;
    float C0 = horner8(s0, s1, q);
    float C1 = horner8(s2, s3, q);
    float C2 = horner8(s4, s5, q);
    float C3 = horner8(s6, s7, q);
    return fmaf(fmaf(fmaf(C3, q8, C2), q8, C1), q8, C0);
}

__device__ __forceinline__ float pow32(float x) {
    float a2 = x * x, a4 = a2 * a2, a8 = a4 * a4, a16 = a8 * a8;
    return a16 * a16;
}

__global__ __launch_bounds__(THREADS)
void poly_tc_kernel(const float* __restrict__ xg,
                    const float* __restrict__ wg,
                    float* __restrict__ out,
                    int ntiles) {
    __shared__ __align__(128) unsigned char smW[32 * 128];
    __shared__ __align__(128) unsigned char smS[NWARP][2][S_WARP_BYTES];

    const int tid  = threadIdx.x;
    const int wid  = tid >> 5;
    const int lane = tid & 31;
    const int g    = lane >> 2;
    const int cL   = lane & 3;

    // ---- once-per-block prologue: W tiles (swizzled) + B fragments ----
    for (int i = tid; i < 1024; i += THREADS) {
        float v = (i < NCOEF) ? wg[i] : 0.0f;
        __nv_bfloat16 hb = __float2bfloat16_rn(v);
        __nv_bfloat16 lb = __float2bfloat16_rn(v - __bfloat162float(hb));
        int n = i >> 5, k = i & 31;
        int ch = k >> 3, byo = (k & 7) * 2;
        *(__nv_bfloat16*)(smW + n * 128 + ((ch ^ (n & 7)) & 7) * 16 + byo) = hb;
        *(__nv_bfloat16*)(smW + n * 128 + (((ch + 4) ^ (n & 7)) & 7) * 16 + byo) = lb;
    }
    __syncthreads();

    uint32_t bf[2][4][2][2];   // [part][t][h][2]
    {
        const uint32_t wbase = cvta_s(smW);
        const int lr = lane & 15;
        #pragma unroll
        for (int part = 0; part < 2; part++)
            #pragma unroll
            for (int t = 0; t < 4; t++)
                #pragma unroll
                for (int h = 0; h < 2; h++) {
                    int row = 8 * t + (lr & 7);
                    int ch  = part * 4 + 2 * h + (lr >> 3);
                    uint32_t addr = wbase + row * 128 + ((ch ^ (row & 7)) & 7) * 16;
                    ldm_x2(bf[part][t][h][0], bf[part][t][h][1], addr);
                }
    }

    // Store base: row g, chunk c' = 4u + t at 144*row + 64u + 16t + 8e
    const uint32_t sbA = cvta_s(smS[wid][0]);
    const uint32_t sbB = cvta_s(smS[wid][1]);
    const uint32_t soff = (uint32_t)(g * SROW + 64 * (cL >> 1) + 8 * (cL & 1));
    const uint32_t sb0A = sbA + soff, sb0B = sbB + soff;
    const uint32_t rbA  = sbA + (uint32_t)(lane * SROW);
    const uint32_t rbB  = sbB + (uint32_t)(lane * SROW);

    const int warp_gid = blockIdx.x * NWARP + wid;
    const int stride   = gridDim.x * NWARP;

    // Preload tile-A x state (own x in xA; 4 fragment-row x's in xeA)
    float xA = 0.0f, xeA[4] = {0, 0, 0, 0};
    if (warp_gid < ntiles) {
        const float* p = xg + warp_gid * 32;
        xA = p[lane];
        xeA[0] = p[g];      xeA[1] = p[g + 8];
        xeA[2] = p[g + 16]; xeA[3] = p[g + 24];
    }

    #pragma unroll 1
    for (int tA = warp_gid; tA < ntiles; tA += 2 * stride) {
        const int tB = tA + stride;
        const bool hasB = (tB < ntiles);

        // 1. issue tile-B x loads now; latency covered by A's compute
        float xB = 0.0f, xeB[4] = {0, 0, 0, 0};
        if (hasB) {
            const float* p = xg + tB * 32;
            xB = p[lane];
            xeB[0] = p[g];      xeB[1] = p[g + 8];
            xeB[2] = p[g + 16]; xeB[3] = p[g + 24];
        }
        const float qA = pow32(xA);

        __syncwarp();   // prior iteration's epilogue reads done

        // 2. stream A: frags + 48 mma + S stores
        MMA_M(sb0A, xeA, 0)
        MMA_M(sb0A, xeA, 1)

        // 3. prefetch next-A x state (needed next iteration)
        const int tN = tA + 2 * stride;
        float xAn = 0.0f, xeAn[4] = {0, 0, 0, 0};
        if (tN < ntiles) {
            const float* p = xg + tN * 32;
            xAn = p[lane];
            xeAn[0] = p[g];      xeAn[1] = p[g + 8];
            xeAn[2] = p[g + 16]; xeAn[3] = p[g + 24];
        }

        // 4. stream B
        if (hasB) {
            MMA_M(sb0B, xeB, 0)
            MMA_M(sb0B, xeB, 1)
        }
        const float qB = pow32(xB);

        __syncwarp();   // all S stores visible

        // 5. epilogues
        out[tA * 32 + lane] = epilogue(rbA, qA);
        if (hasB) out[tB * 32 + lane] = epilogue(rbB, qB);

        xA = xAn;
        xeA[0] = xeAn[0]; xeA[1] = xeAn[1];
        xeA[2] = xeAn[2]; xeA[3] = xeAn[3];
    }
}

extern "C" void kernel_launch(void* const* d_in, const int* in_sizes, int n_in,
                              void* d_out, int out_size) {
    const float* x = (const float*)d_in[0];   // (512, 1024) fp32
    const float* w = (const float*)d_in[1];   // (1001,) fp32
    float* out = (float*)d_out;

    const int ntiles = out_size / 32;          // 16384 warp-tiles
    poly_tc_kernel<<<GRID, THREADS>>>(x, w, out, ntiles);
}